// round 4
// baseline (speedup 1.0000x reference)
#include <cuda_runtime.h>
#include <cuda_fp16.h>

#define NN 100000
#define EE 1600000
#define DD 64
#define CHUNK 1024
#define NBLK ((NN + CHUNK - 1) / CHUNK)   // 98

// ---- scratch (device globals; no allocation allowed) ----
__device__ int    g_count[NN];
__device__ float  g_dis[NN];
__device__ int    g_rowptr[NN + 1];
__device__ int    g_cursor[NN];
__device__ int    g_bsum[NBLK];
__device__ int2   g_csre[EE];          // {src, w-as-int}
__device__ __half g_hA[NN * DD];
__device__ __half g_hB[NN * DD];

// ---------------- CSR build ----------------

// count in-degrees AND convert x -> fp16 in one kernel (independent work)
__global__ void k_countcvt(const int* __restrict__ ei, const float* __restrict__ x) {
    const int* dst = ei + EE;
    int i = blockIdx.x * blockDim.x + threadIdx.x;
    if (i < EE) atomicAdd(&g_count[dst[i]], 1);
    if (i < NN * DD / 2) {
        float2 v = ((const float2*)x)[i];
        ((__half2*)g_hA)[i] = __float22half2_rn(v);
    }
}

// per-chunk exclusive scan into rowptr (local), chunk totals into g_bsum;
// also computes deg_inv_sqrt.
__global__ void k_scan1() {
    __shared__ int s[CHUNK];
    int t = threadIdx.x;
    int i = blockIdx.x * CHUNK + t;
    int v = (i < NN) ? g_count[i] : 0;
    s[t] = v;
    __syncthreads();
    for (int off = 1; off < CHUNK; off <<= 1) {
        int add = (t >= off) ? s[t - off] : 0;
        __syncthreads();
        s[t] += add;
        __syncthreads();
    }
    if (i < NN) {
        g_rowptr[i] = s[t] - v;  // exclusive (local)
        g_dis[i] = rsqrtf((float)(v + 1));  // +1 self-loop
    }
    if (t == CHUNK - 1) g_bsum[blockIdx.x] = s[t];
}

// each block redundantly scans the 98 block sums (cheap), then offsets its chunk
__global__ void k_scan23() {
    __shared__ int s[NBLK];
    __shared__ int blockOff;
    int t = threadIdx.x;
    if (t < NBLK) s[t] = g_bsum[t];
    __syncthreads();
    if (t == 0) {
        int acc = 0;
        int bid = blockIdx.x;
        for (int b = 0; b < bid; b++) acc += s[b];
        blockOff = acc;
        if (bid == 0) g_rowptr[NN] = EE;
    }
    __syncthreads();
    int i = blockIdx.x * CHUNK + t;
    if (i < NN) {
        int rp = g_rowptr[i] + blockOff;
        g_rowptr[i] = rp;
        g_cursor[i] = rp;
    }
}

__global__ void k_fill(const int* __restrict__ ei) {
    const int* src = ei;
    const int* dst = ei + EE;
    int e = blockIdx.x * blockDim.x + threadIdx.x;
    if (e < EE) {
        int s = src[e], d = dst[e];
        int pos = atomicAdd(&g_cursor[d], 1);
        int2 p;
        p.x = s;
        p.y = __float_as_int(g_dis[s] * g_dis[d]);
        g_csre[pos] = p;
    }
}

// ---------------- fused layer: out = relu( (A_norm @ xin) @ W + b ) -------
// Gathers read fp16 rows, accumulate fp32, GEMM epilogue fp32 (W in smem).
// One warp handles 4 nodes; lane owns 2 channels; 16 gathers in flight.

template <bool RELU, bool OUT16>
__global__ void __launch_bounds__(256) k_layer(
        const __half* __restrict__ xin, const float* __restrict__ W,
        const float* __restrict__ b, __half* __restrict__ out16,
        float* __restrict__ out32) {
    __shared__ float sW[64 * 64];          // 16 KB
    __shared__ float sA[8][4 * 64];        // 8 KB, per-warp aggregate stash
    int t = threadIdx.x;
    for (int i = t * 4; i < 64 * 64; i += 256 * 4)
        *(float4*)&sW[i] = *(const float4*)&W[i];
    __syncthreads();

    int lane = t & 31;
    int wid  = t >> 5;
    int vbase = (blockIdx.x * 8 + wid) * 4;   // 100000 = 3125*8*4 exactly

    const __half2* __restrict__ xin2 = (const __half2*)xin;

    float2 acc[4];
#pragma unroll
    for (int n = 0; n < 4; n++) {
        int v = vbase + n;
        float  dv   = g_dis[v];
        float2 hv   = __half22float2(xin2[(size_t)v * 32 + lane]);
        float  self = dv * dv;
        float  ax = self * hv.x;
        float  ay = self * hv.y;
        int beg = g_rowptr[v];
        int end = g_rowptr[v + 1];
        for (int j = beg; j < end; j += 32) {
            int idx = j + lane;
            int sl = 0; float wl = 0.f;
            if (idx < end) {
                int2 e = g_csre[idx];
                sl = e.x; wl = __int_as_float(e.y);
            }
            int cnt = min(32, end - j);
            int k = 0;
            // 16 independent gathers in flight
            for (; k + 16 <= cnt; k += 16) {
                int s[16]; float w[16]; __half2 h[16];
#pragma unroll
                for (int u = 0; u < 16; u++) {
                    s[u] = __shfl_sync(0xffffffffu, sl, k + u);
                    w[u] = __shfl_sync(0xffffffffu, wl, k + u);
                }
#pragma unroll
                for (int u = 0; u < 16; u++)
                    h[u] = xin2[(size_t)s[u] * 32 + lane];
#pragma unroll
                for (int u = 0; u < 16; u++) {
                    float2 f = __half22float2(h[u]);
                    ax += w[u] * f.x; ay += w[u] * f.y;
                }
            }
            // 8-wide, then 4-wide, then scalar tails
            for (; k + 8 <= cnt; k += 8) {
                int s[8]; float w[8]; __half2 h[8];
#pragma unroll
                for (int u = 0; u < 8; u++) {
                    s[u] = __shfl_sync(0xffffffffu, sl, k + u);
                    w[u] = __shfl_sync(0xffffffffu, wl, k + u);
                }
#pragma unroll
                for (int u = 0; u < 8; u++)
                    h[u] = xin2[(size_t)s[u] * 32 + lane];
#pragma unroll
                for (int u = 0; u < 8; u++) {
                    float2 f = __half22float2(h[u]);
                    ax += w[u] * f.x; ay += w[u] * f.y;
                }
            }
            for (; k + 4 <= cnt; k += 4) {
                int s[4]; float w[4]; __half2 h[4];
#pragma unroll
                for (int u = 0; u < 4; u++) {
                    s[u] = __shfl_sync(0xffffffffu, sl, k + u);
                    w[u] = __shfl_sync(0xffffffffu, wl, k + u);
                }
#pragma unroll
                for (int u = 0; u < 4; u++)
                    h[u] = xin2[(size_t)s[u] * 32 + lane];
#pragma unroll
                for (int u = 0; u < 4; u++) {
                    float2 f = __half22float2(h[u]);
                    ax += w[u] * f.x; ay += w[u] * f.y;
                }
            }
            for (; k < cnt; k++) {
                int   sk = __shfl_sync(0xffffffffu, sl, k);
                float wk = __shfl_sync(0xffffffffu, wl, k);
                float2 hs = __half22float2(xin2[(size_t)sk * 32 + lane]);
                ax += wk * hs.x; ay += wk * hs.y;
            }
        }
        acc[n].x = ax; acc[n].y = ay;
    }

    // stash aggregates, then GEMM epilogue: y[n] = acc[n] @ W + b
#pragma unroll
    for (int n = 0; n < 4; n++)
        *(float2*)&sA[wid][n * 64 + lane * 2] = acc[n];
    __syncwarp();

    float2 bb = *(const float2*)(b + lane * 2);
    float2 y0 = bb, y1 = bb, y2 = bb, y3 = bb;
#pragma unroll 8
    for (int k = 0; k < 64; k++) {
        float2 wk = *(const float2*)&sW[k * 64 + lane * 2];
        float a0 = sA[wid][0 * 64 + k];
        float a1 = sA[wid][1 * 64 + k];
        float a2 = sA[wid][2 * 64 + k];
        float a3 = sA[wid][3 * 64 + k];
        y0.x += a0 * wk.x; y0.y += a0 * wk.y;
        y1.x += a1 * wk.x; y1.y += a1 * wk.y;
        y2.x += a2 * wk.x; y2.y += a2 * wk.y;
        y3.x += a3 * wk.x; y3.y += a3 * wk.y;
    }
    if (RELU) {
        y0.x = fmaxf(y0.x, 0.f); y0.y = fmaxf(y0.y, 0.f);
        y1.x = fmaxf(y1.x, 0.f); y1.y = fmaxf(y1.y, 0.f);
        y2.x = fmaxf(y2.x, 0.f); y2.y = fmaxf(y2.y, 0.f);
        y3.x = fmaxf(y3.x, 0.f); y3.y = fmaxf(y3.y, 0.f);
    }
    if (OUT16) {
        __half2* o2 = (__half2*)out16;
        o2[(size_t)(vbase + 0) * 32 + lane] = __float22half2_rn(y0);
        o2[(size_t)(vbase + 1) * 32 + lane] = __float22half2_rn(y1);
        o2[(size_t)(vbase + 2) * 32 + lane] = __float22half2_rn(y2);
        o2[(size_t)(vbase + 3) * 32 + lane] = __float22half2_rn(y3);
    } else {
        *(float2*)(out32 + (size_t)(vbase + 0) * 64 + lane * 2) = y0;
        *(float2*)(out32 + (size_t)(vbase + 1) * 64 + lane * 2) = y1;
        *(float2*)(out32 + (size_t)(vbase + 2) * 64 + lane * 2) = y2;
        *(float2*)(out32 + (size_t)(vbase + 3) * 64 + lane * 2) = y3;
    }
}

// ---------------- launch ----------------

extern "C" void kernel_launch(void* const* d_in, const int* in_sizes, int n_in,
                              void* d_out, int out_size) {
    const float* x  = (const float*)d_in[0];
    const int*   ei = (const int*)d_in[1];
    const float* W1 = (const float*)d_in[2];
    const float* b1 = (const float*)d_in[3];
    const float* W2 = (const float*)d_in[4];
    const float* b2 = (const float*)d_in[5];
    const float* W3 = (const float*)d_in[6];
    const float* b3 = (const float*)d_in[7];
    float* out = (float*)d_out;

    __half *hA, *hB;
    int *cnt;
    cudaGetSymbolAddress((void**)&hA, g_hA);
    cudaGetSymbolAddress((void**)&hB, g_hB);
    cudaGetSymbolAddress((void**)&cnt, g_count);

    const int T = 256;
    // CSR build (+ fp16 convert fused into first kernel)
    cudaMemsetAsync(cnt, 0, NN * sizeof(int));
    {
        int work = NN * DD / 2;            // 3.2M > EE
        k_countcvt<<<(work + T - 1) / T, T>>>(ei, x);
    }
    k_scan1<<<NBLK, CHUNK>>>();
    k_scan23<<<NBLK, CHUNK>>>();
    k_fill<<<(EE + T - 1) / T, T>>>(ei);

    const int LAYER_GRID = NN / 32;   // 3125: 8 warps/block * 4 nodes/warp

    k_layer<true,  true ><<<LAYER_GRID, T>>>(hA, W1, b1, hB, nullptr);
    k_layer<true,  true ><<<LAYER_GRID, T>>>(hB, W2, b2, hA, nullptr);
    k_layer<false, false><<<LAYER_GRID, T>>>(hA, W3, b3, nullptr, out);
}

// round 6
// speedup vs baseline: 1.0083x; 1.0083x over previous
#include <cuda_runtime.h>
#include <cuda_fp16.h>

#define NN 100000
#define EE 1600000
#define DD 64
#define CHUNK 1024
#define NBLK ((NN + CHUNK - 1) / CHUNK)   // 98

// ---- scratch (device globals; no allocation allowed) ----
__device__ int    g_count[NN];
__device__ float  g_dis[NN];
__device__ int    g_rowptr[NN + 1];
__device__ int    g_cursor[NN];
__device__ int    g_bsum[NBLK];
__device__ int2   g_csre[EE];          // {src, dis[src]-as-int}
__device__ __half g_hA[NN * DD];
__device__ __half g_hB[NN * DD];

// ---------------- CSR build ----------------

// count in-degrees AND convert x -> fp16 in one kernel (independent work)
__global__ void k_countcvt(const int* __restrict__ ei, const float* __restrict__ x) {
    const int* dst = ei + EE;
    int i = blockIdx.x * blockDim.x + threadIdx.x;
    if (i < EE) atomicAdd(&g_count[dst[i]], 1);
    if (i < NN * DD / 2) {
        float2 v = ((const float2*)x)[i];
        ((__half2*)g_hA)[i] = __float22half2_rn(v);
    }
}

// per-chunk exclusive scan into rowptr (local), chunk totals into g_bsum;
// also computes deg_inv_sqrt.
__global__ void k_scan1() {
    __shared__ int s[CHUNK];
    int t = threadIdx.x;
    int i = blockIdx.x * CHUNK + t;
    int v = (i < NN) ? g_count[i] : 0;
    s[t] = v;
    __syncthreads();
    for (int off = 1; off < CHUNK; off <<= 1) {
        int add = (t >= off) ? s[t - off] : 0;
        __syncthreads();
        s[t] += add;
        __syncthreads();
    }
    if (i < NN) {
        g_rowptr[i] = s[t] - v;  // exclusive (local)
        g_dis[i] = rsqrtf((float)(v + 1));  // +1 self-loop
    }
    if (t == CHUNK - 1) g_bsum[blockIdx.x] = s[t];
}

// each block redundantly scans the 98 block sums, then offsets its chunk
__global__ void k_scan23() {
    __shared__ int s[NBLK];
    __shared__ int blockOff;
    int t = threadIdx.x;
    if (t < NBLK) s[t] = g_bsum[t];
    __syncthreads();
    if (t == 0) {
        int acc = 0;
        int bid = blockIdx.x;
        for (int b = 0; b < bid; b++) acc += s[b];
        blockOff = acc;
        if (bid == 0) g_rowptr[NN] = EE;
    }
    __syncthreads();
    int i = blockIdx.x * CHUNK + t;
    if (i < NN) {
        int rp = g_rowptr[i] + blockOff;
        g_rowptr[i] = rp;
        g_cursor[i] = rp;
    }
}

// store {src, dis[src]}; dis[dst] factored out to the layer epilogue
__global__ void k_fill(const int* __restrict__ ei) {
    const int* src = ei;
    const int* dst = ei + EE;
    int e = blockIdx.x * blockDim.x + threadIdx.x;
    if (e < EE) {
        int s = src[e], d = dst[e];
        int pos = atomicAdd(&g_cursor[d], 1);
        int2 p;
        p.x = s;
        p.y = __float_as_int(g_dis[s]);
        g_csre[pos] = p;
    }
}

// ---------------- fused layer: out = relu( (A_norm @ xin) @ W + b ) -------
// out[v] = dv * ( sum_e dis[src]*h[src] + dv*h[v] ), then @W + b.
// One warp = 4 nodes, processed INTERLEAVED: all rowptrs, then all edge-list
// loads, then gathers round-robin across nodes (up to 32 loads in flight).

template <bool RELU, bool OUT16>
__global__ void __launch_bounds__(256) k_layer(
        const __half* __restrict__ xin, const float* __restrict__ W,
        const float* __restrict__ b, __half* __restrict__ out16,
        float* __restrict__ out32) {
    __shared__ float sW[64 * 64];          // 16 KB
    __shared__ float sA[8][4 * 64];        // 8 KB, per-warp aggregate stash
    int t = threadIdx.x;
    for (int i = t * 4; i < 64 * 64; i += 256 * 4)
        *(float4*)&sW[i] = *(const float4*)&W[i];
    __syncthreads();

    int lane = t & 31;
    int wid  = t >> 5;
    int vbase = (blockIdx.x * 8 + wid) * 4;   // 100000 = 3125*8*4 exactly

    const __half2* __restrict__ xin2 = (const __half2*)xin;

    // hop 1: rowptr[vbase .. vbase+4] and dis[vbase .. vbase+3], one shot
    int   rpl = (lane < 5) ? g_rowptr[vbase + lane] : 0;
    float dvl = (lane < 4) ? g_dis[vbase + lane]    : 0.f;
    int rp0 = __shfl_sync(0xffffffffu, rpl, 0);
    int rp1 = __shfl_sync(0xffffffffu, rpl, 1);
    int rp2 = __shfl_sync(0xffffffffu, rpl, 2);
    int rp3 = __shfl_sync(0xffffffffu, rpl, 3);
    int rp4 = __shfl_sync(0xffffffffu, rpl, 4);
    int beg[4] = {rp0, rp1, rp2, rp3};
    int cnt[4] = {rp1 - rp0, rp2 - rp1, rp3 - rp2, rp4 - rp3};
    float dv[4];
#pragma unroll
    for (int n = 0; n < 4; n++) dv[n] = __shfl_sync(0xffffffffu, dvl, n);

    // self features (4 independent loads) ; acc starts at dv*h[v]
    float2 acc[4];
#pragma unroll
    for (int n = 0; n < 4; n++) {
        float2 hv = __half22float2(xin2[(size_t)(vbase + n) * 32 + lane]);
        acc[n].x = dv[n] * hv.x;
        acc[n].y = dv[n] * hv.y;
    }

    // hop 2: first edge batch for ALL 4 nodes (4 independent warp loads)
    int2 e[4];
#pragma unroll
    for (int n = 0; n < 4; n++) {
        int c = min(cnt[n], 32);
        e[n].x = 0; e[n].y = 0;
        if (lane < c) e[n] = g_csre[beg[n] + lane];
    }

    // hop 3: gathers, round-robin across nodes, 8-deep per node per step
    int m = max(max(min(cnt[0], 32), min(cnt[1], 32)),
                max(min(cnt[2], 32), min(cnt[3], 32)));
    for (int k = 0; k < m; k += 8) {
#pragma unroll
        for (int n = 0; n < 4; n++) {
            if (k < cnt[n]) {            // warp-uniform branch
                int s[8]; float w[8]; __half2 h[8];
#pragma unroll
                for (int u = 0; u < 8; u++) {
                    s[u] = __shfl_sync(0xffffffffu, e[n].x, k + u);
                    w[u] = __shfl_sync(0xffffffffu, __int_as_float(e[n].y), k + u);
                }
#pragma unroll
                for (int u = 0; u < 8; u++)
                    h[u] = xin2[(size_t)s[u] * 32 + lane];
#pragma unroll
                for (int u = 0; u < 8; u++) {
                    float2 f = __half22float2(h[u]);
                    acc[n].x += w[u] * f.x;
                    acc[n].y += w[u] * f.y;
                }
            }
        }
    }

    // rare overflow: degree > 32
#pragma unroll
    for (int n = 0; n < 4; n++) {
        int end = beg[n] + cnt[n];
        for (int j = beg[n] + 32; j < end; j += 32) {
            int idx = j + lane;
            int sl = 0; float wl = 0.f;
            if (idx < end) {
                int2 p = g_csre[idx];
                sl = p.x; wl = __int_as_float(p.y);
            }
            int c = min(32, end - j);
            for (int k = 0; k < c; k += 8) {
                int kk = min(8, c - k);
#pragma unroll
                for (int u = 0; u < 8; u++) {
                    if (u < kk) {
                        int   sk = __shfl_sync(0xffffffffu, sl, k + u);
                        float wk = __shfl_sync(0xffffffffu, wl, k + u);
                        float2 f = __half22float2(xin2[(size_t)sk * 32 + lane]);
                        acc[n].x += wk * f.x;
                        acc[n].y += wk * f.y;
                    }
                }
            }
        }
    }

    // scale by dv (factored dis[dst]) and stash
#pragma unroll
    for (int n = 0; n < 4; n++) {
        acc[n].x *= dv[n];
        acc[n].y *= dv[n];
        *(float2*)&sA[wid][n * 64 + lane * 2] = acc[n];
    }
    __syncwarp();

    // GEMM epilogue: y[n] = acc[n] @ W + b
    float2 bb = *(const float2*)(b + lane * 2);
    float2 y0 = bb, y1 = bb, y2 = bb, y3 = bb;
#pragma unroll 8
    for (int k = 0; k < 64; k++) {
        float2 wk = *(const float2*)&sW[k * 64 + lane * 2];
        float a0 = sA[wid][0 * 64 + k];
        float a1 = sA[wid][1 * 64 + k];
        float a2 = sA[wid][2 * 64 + k];
        float a3 = sA[wid][3 * 64 + k];
        y0.x += a0 * wk.x; y0.y += a0 * wk.y;
        y1.x += a1 * wk.x; y1.y += a1 * wk.y;
        y2.x += a2 * wk.x; y2.y += a2 * wk.y;
        y3.x += a3 * wk.x; y3.y += a3 * wk.y;
    }
    if (RELU) {
        y0.x = fmaxf(y0.x, 0.f); y0.y = fmaxf(y0.y, 0.f);
        y1.x = fmaxf(y1.x, 0.f); y1.y = fmaxf(y1.y, 0.f);
        y2.x = fmaxf(y2.x, 0.f); y2.y = fmaxf(y2.y, 0.f);
        y3.x = fmaxf(y3.x, 0.f); y3.y = fmaxf(y3.y, 0.f);
    }
    if (OUT16) {
        __half2* o2 = (__half2*)out16;
        o2[(size_t)(vbase + 0) * 32 + lane] = __float22half2_rn(y0);
        o2[(size_t)(vbase + 1) * 32 + lane] = __float22half2_rn(y1);
        o2[(size_t)(vbase + 2) * 32 + lane] = __float22half2_rn(y2);
        o2[(size_t)(vbase + 3) * 32 + lane] = __float22half2_rn(y3);
    } else {
        *(float2*)(out32 + (size_t)(vbase + 0) * 64 + lane * 2) = y0;
        *(float2*)(out32 + (size_t)(vbase + 1) * 64 + lane * 2) = y1;
        *(float2*)(out32 + (size_t)(vbase + 2) * 64 + lane * 2) = y2;
        *(float2*)(out32 + (size_t)(vbase + 3) * 64 + lane * 2) = y3;
    }
}

// ---------------- launch ----------------

extern "C" void kernel_launch(void* const* d_in, const int* in_sizes, int n_in,
                              void* d_out, int out_size) {
    const float* x  = (const float*)d_in[0];
    const int*   ei = (const int*)d_in[1];
    const float* W1 = (const float*)d_in[2];
    const float* b1 = (const float*)d_in[3];
    const float* W2 = (const float*)d_in[4];
    const float* b2 = (const float*)d_in[5];
    const float* W3 = (const float*)d_in[6];
    const float* b3 = (const float*)d_in[7];
    float* out = (float*)d_out;

    __half *hA, *hB;
    int *cnt;
    cudaGetSymbolAddress((void**)&hA, g_hA);
    cudaGetSymbolAddress((void**)&hB, g_hB);
    cudaGetSymbolAddress((void**)&cnt, g_count);

    const int T = 256;
    // CSR build (+ fp16 convert fused into first kernel)
    cudaMemsetAsync(cnt, 0, NN * sizeof(int));
    {
        int work = NN * DD / 2;            // 3.2M > EE
        k_countcvt<<<(work + T - 1) / T, T>>>(ei, x);
    }
    k_scan1<<<NBLK, CHUNK>>>();
    k_scan23<<<NBLK, CHUNK>>>();
    k_fill<<<(EE + T - 1) / T, T>>>(ei);

    const int LAYER_GRID = NN / 32;   // 3125: 8 warps/block * 4 nodes/warp

    k_layer<true,  true ><<<LAYER_GRID, T>>>(hA, W1, b1, hB, nullptr);
    k_layer<true,  true ><<<LAYER_GRID, T>>>(hB, W2, b2, hA, nullptr);
    k_layer<false, false><<<LAYER_GRID, T>>>(hA, W3, b3, nullptr, out);
}

// round 7
// speedup vs baseline: 1.3346x; 1.3236x over previous
#include <cuda_runtime.h>
#include <cuda_fp16.h>
#include <cstdint>

#define NN 100000
#define EE 1600000
#define DD 64
#define CHUNK 1024
#define NBLK ((NN + CHUNK - 1) / CHUNK)   // 98

// ---- scratch (device globals; no allocation allowed) ----
// g_cntflag: [0,NN) = per-node in-degree counts, [NN,NN+NBLK) = scan flags.
// One memsetAsync zeroes both each run.
__device__ int    g_cntflag[NN + NBLK];
__device__ int    g_agg[NBLK];
__device__ float  g_dis[NN];
__device__ int    g_rowptr[NN + 1];
__device__ int    g_cursor[NN];
__device__ int2   g_csre[EE];          // {src, dis[src]-as-int}
__device__ __half g_hA[NN * DD];
__device__ __half g_hB[NN * DD];

// ---------------- CSR build ----------------

// count in-degrees AND convert x -> fp16 (independent work, one kernel)
__global__ void k_countcvt(const int* __restrict__ ei, const float* __restrict__ x) {
    const int* dst = ei + EE;
    int i = blockIdx.x * blockDim.x + threadIdx.x;
    if (i < EE) atomicAdd(&g_cntflag[dst[i]], 1);
    if (i < NN * DD / 2) {
        float2 v = ((const float2*)x)[i];
        ((__half2*)g_hA)[i] = __float22half2_rn(v);
    }
}

// single-pass scan with decoupled lookback (all 98 blocks co-resident):
// local Hillis-Steele, publish aggregate+flag, sum all predecessor aggs.
__global__ void k_scan() {
    __shared__ int s[CHUNK];
    __shared__ int exoff;
    volatile int* flag = (volatile int*)(g_cntflag + NN);
    int t = threadIdx.x, bid = blockIdx.x;
    int i = bid * CHUNK + t;
    int v = (i < NN) ? g_cntflag[i] : 0;
    s[t] = v;
    if (t == 0) exoff = 0;
    __syncthreads();
    for (int off = 1; off < CHUNK; off <<= 1) {
        int add = (t >= off) ? s[t - off] : 0;
        __syncthreads();
        s[t] += add;
        __syncthreads();
    }
    if (t == CHUNK - 1) {           // publish block aggregate
        g_agg[bid] = s[t];
        __threadfence();
        flag[bid] = 1;
    }
    if (t < bid) {                   // gather predecessors (≤97 spinners)
        while (flag[t] == 0) { }
        int a = *((volatile int*)&g_agg[t]);
        atomicAdd(&exoff, a);
    }
    __syncthreads();
    if (i < NN) {
        int rp = exoff + s[t] - v;   // global exclusive prefix
        g_rowptr[i] = rp;
        g_cursor[i] = rp;
        g_dis[i] = rsqrtf((float)(v + 1));   // +1 self-loop
    }
    if (bid == 0 && t == 0) g_rowptr[NN] = EE;
}

// store {src, dis[src]}; dis[dst] factored into the layer epilogue
__global__ void k_fill(const int* __restrict__ ei) {
    const int* src = ei;
    const int* dst = ei + EE;
    int e = blockIdx.x * blockDim.x + threadIdx.x;
    if (e < EE) {
        int s = src[e], d = dst[e];
        int pos = atomicAdd(&g_cursor[d], 1);
        int2 p;
        p.x = s;
        p.y = __float_as_int(g_dis[s]);
        g_csre[pos] = p;
    }
}

// ---------------- fused layer ----------------
// out = relu( diag(d^-1/2) (A+I) diag(d^-1/2) xin @ W + b )
// Phase 1 (per warp, 4 nodes): acc[v] = dv * (sum_e dis[src]*h[src] + dv*h[v])
// Phase 2 (block, tensor cores): Y[32x64] = Acc[32x64] @ W[64x64] + b via
// mma.sync m16n8k16 fp16 inputs / fp32 accum, fragments through ldmatrix.

#define APAD 72   // fp16 row pitch (144B) -> ldmatrix bank-conflict-free

template <bool RELU, bool OUT16>
__global__ void __launch_bounds__(256) k_layer(
        const __half* __restrict__ xin, const float* __restrict__ W,
        const float* __restrict__ b, __half* __restrict__ out16,
        float* __restrict__ out32) {
    __shared__ __half sWh[64][APAD];   // W in fp16
    __shared__ __half sAh[32][APAD];   // per-block aggregates in fp16
    int t = threadIdx.x;

    // W fp32 -> fp16 into smem (2048 float2s over 256 threads)
    for (int i = t; i < 64 * 32; i += 256) {
        int k = i >> 5;
        int c = (i & 31) * 2;
        float2 w2 = *(const float2*)(W + k * 64 + c);
        *(__half2*)&sWh[k][c] = __float22half2_rn(w2);
    }

    int lane = t & 31;
    int wid  = t >> 5;
    int vblock = blockIdx.x * 32;             // 3125 blocks * 32 nodes
    int vbase  = vblock + wid * 4;

    const __half2* __restrict__ xin2 = (const __half2*)xin;

    // rowptr[vbase..vbase+4] + dis[vbase..vbase+3] in one warp load
    int   rpl = (lane < 5) ? g_rowptr[vbase + lane] : 0;
    float dvl = (lane < 4) ? g_dis[vbase + lane]    : 0.f;
    int rp[5];
#pragma unroll
    for (int q = 0; q < 5; q++) rp[q] = __shfl_sync(0xffffffffu, rpl, q);
    float dv[4];
#pragma unroll
    for (int n = 0; n < 4; n++) dv[n] = __shfl_sync(0xffffffffu, dvl, n);

#pragma unroll
    for (int n = 0; n < 4; n++) {
        int v = vbase + n;
        float2 hv = __half22float2(xin2[(size_t)v * 32 + lane]);
        float ax = dv[n] * hv.x;
        float ay = dv[n] * hv.y;
        int beg = rp[n], end = rp[n + 1];
        for (int j = beg; j < end; j += 32) {
            int idx = j + lane;
            int sl = 0; float wl = 0.f;
            if (idx < end) {
                int2 p = g_csre[idx];
                sl = p.x; wl = __int_as_float(p.y);
            }
            int cnt = min(32, end - j);
            int k = 0;
            for (; k + 8 <= cnt; k += 8) {      // 8 gathers in flight
                int s[8]; float w[8]; __half2 h[8];
#pragma unroll
                for (int u = 0; u < 8; u++) {
                    s[u] = __shfl_sync(0xffffffffu, sl, k + u);
                    w[u] = __shfl_sync(0xffffffffu, wl, k + u);
                }
#pragma unroll
                for (int u = 0; u < 8; u++)
                    h[u] = xin2[(size_t)s[u] * 32 + lane];
#pragma unroll
                for (int u = 0; u < 8; u++) {
                    float2 f = __half22float2(h[u]);
                    ax += w[u] * f.x; ay += w[u] * f.y;
                }
            }
            for (; k + 4 <= cnt; k += 4) {
                int s[4]; float w[4]; __half2 h[4];
#pragma unroll
                for (int u = 0; u < 4; u++) {
                    s[u] = __shfl_sync(0xffffffffu, sl, k + u);
                    w[u] = __shfl_sync(0xffffffffu, wl, k + u);
                }
#pragma unroll
                for (int u = 0; u < 4; u++)
                    h[u] = xin2[(size_t)s[u] * 32 + lane];
#pragma unroll
                for (int u = 0; u < 4; u++) {
                    float2 f = __half22float2(h[u]);
                    ax += w[u] * f.x; ay += w[u] * f.y;
                }
            }
            for (; k < cnt; k++) {
                int   sk = __shfl_sync(0xffffffffu, sl, k);
                float wk = __shfl_sync(0xffffffffu, wl, k);
                float2 f = __half22float2(xin2[(size_t)sk * 32 + lane]);
                ax += wk * f.x; ay += wk * f.y;
            }
        }
        float2 a2; a2.x = dv[n] * ax; a2.y = dv[n] * ay;
        *(__half2*)&sAh[wid * 4 + n][lane * 2] = __float22half2_rn(a2);
    }
    __syncthreads();   // sWh + sAh ready

    // ---- tensor-core epilogue: warp w -> rows (w&1)*16..+15, cols (w>>1)*16..+15
    int mrow = (wid & 1) * 16;
    int ncol = (wid >> 1) * 16;

    float d0[4] = {0.f, 0.f, 0.f, 0.f};    // m16n8 tile at ncol
    float d1[4] = {0.f, 0.f, 0.f, 0.f};    // m16n8 tile at ncol+8

    // A-fragment ldmatrix address: 4 8x8 blocks (r0:m0k0, r1:m8k0, r2:m0k8, r3:m8k8)
    int qa = lane >> 3;         // 0..3
    int ra = lane & 7;
#pragma unroll
    for (int ks = 0; ks < 4; ks++) {
        int arow = mrow + ra + (qa & 1) * 8;
        int acol = ks * 16 + (qa >> 1) * 8;
        uint32_t aaddr = (uint32_t)__cvta_generic_to_shared(&sAh[arow][acol]);
        uint32_t a0, a1, a2, a3;
        asm volatile("ldmatrix.sync.aligned.m8n8.x4.shared.b16 {%0,%1,%2,%3}, [%4];"
                     : "=r"(a0), "=r"(a1), "=r"(a2), "=r"(a3) : "r"(aaddr));

        // B fragments: ldmatrix x2 trans on row-major W[k][n]
        int brow = ks * 16 + (lane & 15);      // lanes 0-15 used
        uint32_t baddr0 = (uint32_t)__cvta_generic_to_shared(&sWh[brow][ncol]);
        uint32_t baddr1 = (uint32_t)__cvta_generic_to_shared(&sWh[brow][ncol + 8]);
        uint32_t b0, b1, b2, b3;
        asm volatile("ldmatrix.sync.aligned.m8n8.x2.trans.shared.b16 {%0,%1}, [%2];"
                     : "=r"(b0), "=r"(b1) : "r"(baddr0));
        asm volatile("ldmatrix.sync.aligned.m8n8.x2.trans.shared.b16 {%0,%1}, [%2];"
                     : "=r"(b2), "=r"(b3) : "r"(baddr1));

        asm volatile("mma.sync.aligned.m16n8k16.row.col.f32.f16.f16.f32 "
                     "{%0,%1,%2,%3}, {%4,%5,%6,%7}, {%8,%9}, {%0,%1,%2,%3};"
                     : "+f"(d0[0]), "+f"(d0[1]), "+f"(d0[2]), "+f"(d0[3])
                     : "r"(a0), "r"(a1), "r"(a2), "r"(a3), "r"(b0), "r"(b1));
        asm volatile("mma.sync.aligned.m16n8k16.row.col.f32.f16.f16.f32 "
                     "{%0,%1,%2,%3}, {%4,%5,%6,%7}, {%8,%9}, {%0,%1,%2,%3};"
                     : "+f"(d1[0]), "+f"(d1[1]), "+f"(d1[2]), "+f"(d1[3])
                     : "r"(a0), "r"(a1), "r"(a2), "r"(a3), "r"(b2), "r"(b3));
    }

    // bias + relu + store.  D fragment: lane -> rows mrow+lane/4 (+8),
    // cols ncol + (lane%4)*2 (+1); second tile at +8 cols.
    int drow = vblock + mrow + (lane >> 2);
    int dcol = ncol + (lane & 3) * 2;
    float2 bb0 = *(const float2*)(b + dcol);
    float2 bb1 = *(const float2*)(b + dcol + 8);
    float2 y00 = {d0[0] + bb0.x, d0[1] + bb0.y};   // row drow,   cols dcol
    float2 y01 = {d1[0] + bb1.x, d1[1] + bb1.y};   // row drow,   cols dcol+8
    float2 y10 = {d0[2] + bb0.x, d0[3] + bb0.y};   // row drow+8, cols dcol
    float2 y11 = {d1[2] + bb1.x, d1[3] + bb1.y};   // row drow+8, cols dcol+8
    if (RELU) {
        y00.x = fmaxf(y00.x, 0.f); y00.y = fmaxf(y00.y, 0.f);
        y01.x = fmaxf(y01.x, 0.f); y01.y = fmaxf(y01.y, 0.f);
        y10.x = fmaxf(y10.x, 0.f); y10.y = fmaxf(y10.y, 0.f);
        y11.x = fmaxf(y11.x, 0.f); y11.y = fmaxf(y11.y, 0.f);
    }
    if (OUT16) {
        __half2* o2 = (__half2*)out16;
        o2[(size_t)drow * 32 + (dcol >> 1)]           = __float22half2_rn(y00);
        o2[(size_t)drow * 32 + ((dcol + 8) >> 1)]     = __float22half2_rn(y01);
        o2[(size_t)(drow + 8) * 32 + (dcol >> 1)]     = __float22half2_rn(y10);
        o2[(size_t)(drow + 8) * 32 + ((dcol + 8) >> 1)] = __float22half2_rn(y11);
    } else {
        *(float2*)(out32 + (size_t)drow * 64 + dcol)           = y00;
        *(float2*)(out32 + (size_t)drow * 64 + dcol + 8)       = y01;
        *(float2*)(out32 + (size_t)(drow + 8) * 64 + dcol)     = y10;
        *(float2*)(out32 + (size_t)(drow + 8) * 64 + dcol + 8) = y11;
    }
}

// ---------------- launch ----------------

extern "C" void kernel_launch(void* const* d_in, const int* in_sizes, int n_in,
                              void* d_out, int out_size) {
    const float* x  = (const float*)d_in[0];
    const int*   ei = (const int*)d_in[1];
    const float* W1 = (const float*)d_in[2];
    const float* b1 = (const float*)d_in[3];
    const float* W2 = (const float*)d_in[4];
    const float* b2 = (const float*)d_in[5];
    const float* W3 = (const float*)d_in[6];
    const float* b3 = (const float*)d_in[7];
    float* out = (float*)d_out;

    __half *hA, *hB;
    int *cntflag;
    cudaGetSymbolAddress((void**)&hA, g_hA);
    cudaGetSymbolAddress((void**)&hB, g_hB);
    cudaGetSymbolAddress((void**)&cntflag, g_cntflag);

    const int T = 256;
    cudaMemsetAsync(cntflag, 0, (NN + NBLK) * sizeof(int));
    {
        int work = NN * DD / 2;            // 3.2M > EE
        k_countcvt<<<(work + T - 1) / T, T>>>(ei, x);
    }
    k_scan<<<NBLK, CHUNK>>>();
    k_fill<<<(EE + T - 1) / T, T>>>(ei);

    const int LAYER_GRID = NN / 32;   // 3125 blocks, 32 nodes each

    k_layer<true,  true ><<<LAYER_GRID, T>>>(hA, W1, b1, hB, nullptr);
    k_layer<true,  true ><<<LAYER_GRID, T>>>(hB, W2, b2, hA, nullptr);
    k_layer<false, false><<<LAYER_GRID, T>>>(hA, W3, b3, nullptr, out);
}